// round 1
// baseline (speedup 1.0000x reference)
#include <cuda_runtime.h>

// Problem constants (from reference): shape (8,16,6,256,256)
// rows = 8*16*6 = 768, row_len = 256*256 = 65536
#define ROW_LEN   65536
#define ROW_LEN4  (ROW_LEN / 4)
#define THREADS   1024
#define MAX_ROWS  4096

// Scratch for per-row r values (device global: no allocations allowed).
__device__ float g_row_r[MAX_ROWS];

__global__ __launch_bounds__(THREADS, 1)
void row_stats_kernel(const float* __restrict__ X, const float* __restrict__ Y) {
    const size_t row = blockIdx.x;
    const float4* __restrict__ x4 = reinterpret_cast<const float4*>(X) + row * ROW_LEN4;
    const float4* __restrict__ y4 = reinterpret_cast<const float4*>(Y) + row * ROW_LEN4;

    float sx = 0.f, sy = 0.f, sxx = 0.f, syy = 0.f, sxy = 0.f;

    // 16384 float4 per row / 1024 threads = 16 iterations per thread.
    #pragma unroll 4
    for (int i = threadIdx.x; i < ROW_LEN4; i += THREADS) {
        float4 a = __ldg(&x4[i]);
        float4 b = __ldg(&y4[i]);
        sx  += a.x + a.y + a.z + a.w;
        sy  += b.x + b.y + b.z + b.w;
        sxx += a.x * a.x + a.y * a.y + a.z * a.z + a.w * a.w;
        syy += b.x * b.x + b.y * b.y + b.z * b.z + b.w * b.w;
        sxy += a.x * b.x + a.y * b.y + a.z * b.z + a.w * b.w;
    }

    // Warp reduce 5 values.
    #pragma unroll
    for (int o = 16; o > 0; o >>= 1) {
        sx  += __shfl_xor_sync(0xFFFFFFFFu, sx,  o);
        sy  += __shfl_xor_sync(0xFFFFFFFFu, sy,  o);
        sxx += __shfl_xor_sync(0xFFFFFFFFu, sxx, o);
        syy += __shfl_xor_sync(0xFFFFFFFFu, syy, o);
        sxy += __shfl_xor_sync(0xFFFFFFFFu, sxy, o);
    }

    __shared__ float sm[5][32];
    const int lane = threadIdx.x & 31;
    const int wid  = threadIdx.x >> 5;
    if (lane == 0) {
        sm[0][wid] = sx; sm[1][wid] = sy; sm[2][wid] = sxx;
        sm[3][wid] = syy; sm[4][wid] = sxy;
    }
    __syncthreads();

    if (wid == 0) {
        // 1024 threads -> exactly 32 warps, so all 32 slots are valid.
        sx  = sm[0][lane];
        sy  = sm[1][lane];
        sxx = sm[2][lane];
        syy = sm[3][lane];
        sxy = sm[4][lane];
        #pragma unroll
        for (int o = 16; o > 0; o >>= 1) {
            sx  += __shfl_xor_sync(0xFFFFFFFFu, sx,  o);
            sy  += __shfl_xor_sync(0xFFFFFFFFu, sy,  o);
            sxx += __shfl_xor_sync(0xFFFFFFFFu, sxx, o);
            syy += __shfl_xor_sync(0xFFFFFFFFu, syy, o);
            sxy += __shfl_xor_sync(0xFFFFFFFFu, sxy, o);
        }
        if (lane == 0) {
            const float n = (float)ROW_LEN;
            // Centered second moments (the 1/(n-1) factor cancels in the ratio).
            float mxx = sxx - sx * sx / n;
            float myy = syy - sy * sy / n;
            float mxy = sxy - sx * sy / n;
            // r = 1 - 0.5*(Var(x+y)-Var(x)-Var(y))/sqrt(|Var(x)Var(y)|)
            //   = 1 - Cov(x,y)/sqrt(|Var(x)Var(y)|)
            float r = 1.0f - mxy * rsqrtf(fabsf(mxx * myy));
            g_row_r[row] = r;
        }
    }
}

__global__ void final_reduce_kernel(float* __restrict__ out, int rows) {
    float s = 0.f;
    for (int i = threadIdx.x; i < rows; i += blockDim.x)
        s += g_row_r[i];
    #pragma unroll
    for (int o = 16; o > 0; o >>= 1)
        s += __shfl_xor_sync(0xFFFFFFFFu, s, o);
    __shared__ float sm[32];
    const int lane = threadIdx.x & 31;
    const int wid  = threadIdx.x >> 5;
    if (lane == 0) sm[wid] = s;
    __syncthreads();
    if (wid == 0) {
        int nw = (blockDim.x + 31) >> 5;
        s = (lane < nw) ? sm[lane] : 0.f;
        #pragma unroll
        for (int o = 16; o > 0; o >>= 1)
            s += __shfl_xor_sync(0xFFFFFFFFu, s, o);
        if (lane == 0) out[0] = s / (float)rows;
    }
}

extern "C" void kernel_launch(void* const* d_in, const int* in_sizes, int n_in,
                              void* d_out, int out_size) {
    const float* X = (const float*)d_in[0];
    const float* Y = (const float*)d_in[1];
    float* out = (float*)d_out;

    const int rows = in_sizes[0] / ROW_LEN;  // 768 for the given shape

    row_stats_kernel<<<rows, THREADS>>>(X, Y);
    final_reduce_kernel<<<1, 1024>>>(out, rows);
}